// round 11
// baseline (speedup 1.0000x reference)
#include <cuda_runtime.h>
#include <cuda_bf16.h>
#include <cstdint>

// Shapes (fixed per problem)
#define BB 8
#define TT 2048
#define CC 768
#define WDIM 512
#define TD 384
#define CD 3072
#define ROWS (BB * TT)          // 16384

// weight pack offsets (elements), layout (K, N) n-contiguous
#define OFF_G12 0               // fused g1|g2, (768, 1536)
#define OFF_M1 1179648
#define OFF_M2 1327104
#define OFF_GS 1474560
#define OFF_MS 3833856
#define OFF_R1 5013504
#define OFF_R2 5603328
#define WTOT   5898240

// bias pack offsets
#define BI_G12 0
#define BI_GS  1536
#define BI_R1  (1536 + CD)

typedef __nv_bfloat16 bf16;

// ---------------- scratch (device globals; no allocation allowed) ----------
__device__ float BUF_XLN[ROWS * CC];       // fp32 ln1 out (residual for step x2)
__device__ float BUF_X2 [ROWS * CC];       // fp32 (residual for ms + ln2 in)
__device__ float BUF_S1 [BB * TD];
__device__ float BUF_S2 [BB * TD];
__device__ float BUF_SS [BB * (CD/2)];
__device__ float BUF_BI [1536 + CD + CC];  // interleaved biases g12, gs, r1

__device__ bf16 S_XLNh[ROWS * CC],      S_XLNl[ROWS * CC];
__device__ bf16 S_ACTh[ROWS * (CD/2)],  S_ACTl[ROWS * (CD/2)];
__device__ bf16 S_A1h [ROWS * TD],      S_A1l [ROWS * TD];
__device__ bf16 S_A2h [ROWS * TD],      S_A2l [ROWS * TD];
__device__ bf16 S_H1h [BB * TD * TT],   S_H1l [BB * TD * TT];   // (b,d,t)
__device__ bf16 S_H2h [ROWS * TD],      S_H2l [ROWS * TD];      // (b,t,d)
__device__ bf16 S_MIXh[BB * TD * CC],   S_MIXl[BB * TD * CC];   // (b,d,c)
__device__ bf16 S_X3h [ROWS * CC],      S_X3l [ROWS * CC];
__device__ bf16 S_Wh  [WTOT],           S_Wl  [WTOT];

// ---------------- helpers ---------------------------------------------------
__device__ __forceinline__ float gelu_f(float v) {
    return 0.5f * v * (1.0f + erff(v * 0.70710678118654752f));
}
__device__ __forceinline__ void split_bf16(float v, bf16& h, bf16& l) {
    h = __float2bfloat16_rn(v);
    l = __float2bfloat16_rn(v - __bfloat162float(h));
}
__device__ __forceinline__ void cp16(void* smem, const void* gmem) {
    uint32_t s = (uint32_t)__cvta_generic_to_shared(smem);
    asm volatile("cp.async.cg.shared.global [%0], [%1], 16;" :: "r"(s), "l"(gmem));
}
__device__ __forceinline__ void cp_commit() { asm volatile("cp.async.commit_group;"); }

__device__ __forceinline__ void ldsm4(uint32_t* r, const void* p) {
    uint32_t a = (uint32_t)__cvta_generic_to_shared(p);
    asm volatile("ldmatrix.sync.aligned.m8n8.x4.shared.b16 {%0,%1,%2,%3}, [%4];"
                 : "=r"(r[0]), "=r"(r[1]), "=r"(r[2]), "=r"(r[3]) : "r"(a));
}
__device__ __forceinline__ void ldsm4t(uint32_t* r, const void* p) {
    uint32_t a = (uint32_t)__cvta_generic_to_shared(p);
    asm volatile("ldmatrix.sync.aligned.m8n8.x4.trans.shared.b16 {%0,%1,%2,%3}, [%4];"
                 : "=r"(r[0]), "=r"(r[1]), "=r"(r[2]), "=r"(r[3]) : "r"(a));
}
__device__ __forceinline__ void mma_bf16(float* d, const uint32_t* a, const uint32_t* b) {
    asm volatile(
        "mma.sync.aligned.m16n8k16.row.col.f32.bf16.bf16.f32 "
        "{%0,%1,%2,%3}, {%4,%5,%6,%7}, {%8,%9}, {%0,%1,%2,%3};"
        : "+f"(d[0]), "+f"(d[1]), "+f"(d[2]), "+f"(d[3])
        : "r"(a[0]), "r"(a[1]), "r"(a[2]), "r"(a[3]), "r"(b[0]), "r"(b[1]));
}

// ---------------- LayerNorm (+ bf16 split output) ----------------------------
__global__ void ln_split_kernel(const float* __restrict__ x,
                                const float* __restrict__ g,
                                const float* __restrict__ b,
                                float* __restrict__ yf,
                                bf16* __restrict__ yh,
                                bf16* __restrict__ yl, int C) {
    __shared__ float red[2][8];
    long row = blockIdx.x;
    const float* xr = x + row * C;
    float s = 0.f, s2 = 0.f;
    for (int c = threadIdx.x; c < C; c += blockDim.x) {
        float v = xr[c];
        s += v; s2 += v * v;
    }
    #pragma unroll
    for (int o = 16; o; o >>= 1) {
        s  += __shfl_xor_sync(0xFFFFFFFFu, s,  o);
        s2 += __shfl_xor_sync(0xFFFFFFFFu, s2, o);
    }
    int w = threadIdx.x >> 5, l = threadIdx.x & 31;
    if (l == 0) { red[0][w] = s; red[1][w] = s2; }
    __syncthreads();
    if (threadIdx.x < 32) {
        s  = (l < 8) ? red[0][l] : 0.f;
        s2 = (l < 8) ? red[1][l] : 0.f;
        #pragma unroll
        for (int o = 4; o; o >>= 1) {
            s  += __shfl_xor_sync(0xFFFFFFFFu, s,  o);
            s2 += __shfl_xor_sync(0xFFFFFFFFu, s2, o);
        }
        if (l == 0) { red[0][0] = s; red[1][0] = s2; }
    }
    __syncthreads();
    float mu  = red[0][0] / C;
    float var = red[1][0] / C - mu * mu;
    float inv = rsqrtf(var + 1e-6f);
    for (int c = threadIdx.x; c < C; c += blockDim.x) {
        float v = (xr[c] - mu) * inv * g[c] + b[c];
        if (yf) yf[row * C + c] = v;
        bf16 h, lo;
        split_bf16(v, h, lo);
        yh[row * C + c] = h;
        yl[row * C + c] = lo;
    }
}

// ---------------- plain weight -> hi/lo bf16 split ---------------------------
__global__ void cvt_split_kernel(const float4* __restrict__ in,
                                 bf16* __restrict__ oh,
                                 bf16* __restrict__ ol, int n4) {
    int idx = blockIdx.x * blockDim.x + threadIdx.x;
    if (idx >= n4) return;
    float4 v = in[idx];
    bf16 h[4], l[4];
    split_bf16(v.x, h[0], l[0]); split_bf16(v.y, h[1], l[1]);
    split_bf16(v.z, h[2], l[2]); split_bf16(v.w, h[3], l[3]);
    *(__nv_bfloat162*)(oh + 4L*idx    ) = __nv_bfloat162(h[0], h[1]);
    *(__nv_bfloat162*)(oh + 4L*idx + 2) = __nv_bfloat162(h[2], h[3]);
    *(__nv_bfloat162*)(ol + 4L*idx    ) = __nv_bfloat162(l[0], l[1]);
    *(__nv_bfloat162*)(ol + 4L*idx + 2) = __nv_bfloat162(l[2], l[3]);
}

// ---------------- GLU weight pack: interleave (a_j, gate_j) columns ----------
// In: W (K, H) n-contig, bias b[H]. Out col (coloff+n), ld=ldout.
__global__ void glu_pack_w(const float* __restrict__ W,
                           const float* __restrict__ b,
                           bf16* __restrict__ oh, bf16* __restrict__ ol,
                           float* __restrict__ biasI, long total, int H,
                           int ldout, int coloff) {
    long idx = (long)blockIdx.x * blockDim.x + threadIdx.x;
    if (idx >= total) return;
    long k = idx / H;
    int  n = (int)(idx - k * H);
    int  src = (n & 1) ? (n >> 1) + (H >> 1) : (n >> 1);
    bf16 h, l;
    split_bf16(W[k * H + src], h, l);
    const long o = k * ldout + coloff + n;
    oh[o] = h;
    ol[o] = l;
    if (k == 0) biasI[coloff + n] = b[src];
}

// ---------------- style-projection, k-split across warps ---------------------
// grid (N/64, BB), block (64, 8)
__global__ void style_s_kernel(const float* __restrict__ w,
                               const float* __restrict__ sW,
                               const float* __restrict__ sb,
                               float* __restrict__ out, int sel, int N) {
    __shared__ float red[8][64];
    const int b = blockIdx.y;
    const int n = blockIdx.x * 64 + threadIdx.x;
    const int ky = threadIdx.y;
    const float* wr = w + b * (2 * WDIM) + sel * WDIM;
    float acc = 0.f;
    #pragma unroll 4
    for (int k = ky * 64; k < ky * 64 + 64; k++)
        acc += wr[k] * sW[(long)k * N + n];
    red[ky][threadIdx.x] = acc;
    __syncthreads();
    if (ky == 0) {
        float s = sb[n];
        #pragma unroll
        for (int i = 0; i < 8; i++) s += red[i][threadIdx.x];
        out[b * N + n] = s;
    }
}

// ---------------- bf16x3 mma.sync GEMM --------------------------------------
// C(M,N) = (Ah+Al)(M,K) @ (Bh+Bl)(K,N)  (lo*lo dropped)
// A k-contig (lda), B n-contig (ldb). CTA 128x128x32, 128 thr, 4 warps 2x2,
// warp tile 64x64. 3-stage cp.async pipeline, loads issued before compute.
#define ASTR 40
#define BSTR 136
#define A_BYTES (128 * ASTR * 2)       // 10240 per hi/lo array
#define B_BYTES (32 * BSTR * 2)        // 8704 per hi/lo array
#define STAGEB  (2 * A_BYTES + 2 * B_BYTES)   // 37888
#define SMEMB   (3 * STAGEB)                  // 113664

template <bool GLU, bool GLUPAIR, bool GELU, bool SPLIT, bool TRANSO, bool FP32O>
__global__ __launch_bounds__(128, 2) void gemm_v4(
    const bf16* __restrict__ Ah, const bf16* __restrict__ Al,
    const bf16* __restrict__ Bh, const bf16* __restrict__ Bl,
    const float* __restrict__ bias,
    const float* __restrict__ styleS, const float* __restrict__ styleS2,
    const float* __restrict__ res,
    float* __restrict__ Cf, bf16* __restrict__ Ch, bf16* __restrict__ Cl,
    bf16* __restrict__ Ch2, bf16* __restrict__ Cl2,
    int N, int K, int lda, int ldb,
    long sA, long sB, long sC, long sRes)
{
    extern __shared__ char smem[];

    const int z = blockIdx.z;
    const bf16* Agh = Ah + (long)z * sA;
    const bf16* Agl = Al + (long)z * sA;
    const bf16* Bgh = Bh + (long)z * sB;
    const bf16* Bgl = Bl + (long)z * sB;
    const float* resp = res ? res + (long)z * sRes : nullptr;

    const int m0 = blockIdx.y * 128, n0 = blockIdx.x * 128;
    const int tid = threadIdx.x;
    const int lane = tid & 31, wid = tid >> 5;
    const int wm = wid >> 1, wn = wid & 1;           // 2x2 warp grid, tile 64x64
    const int lr = lane >> 2, lc = lane & 3;

    const int aoffL = (lane & 15) * ASTR + ((lane >> 4) << 3);
    const int boffC = ((lane >> 4) << 3);

    float acc[4][8][4];
    #pragma unroll
    for (int i = 0; i < 4; i++)
        #pragma unroll
        for (int j = 0; j < 8; j++) {
            acc[i][j][0] = 0.f; acc[i][j][1] = 0.f;
            acc[i][j][2] = 0.f; acc[i][j][3] = 0.f;
        }

    auto loadStage = [&](int st, int k0) {
        char* base = smem + st * STAGEB;
        bf16* ah = (bf16*)(base);
        bf16* al = (bf16*)(base + A_BYTES);
        bf16* bh = (bf16*)(base + 2 * A_BYTES);
        bf16* bl = (bf16*)(base + 2 * A_BYTES + B_BYTES);
        #pragma unroll
        for (int i = tid; i < 512; i += 128) {
            const int r = i >> 2, c = i & 3;
            const long go = (long)(m0 + r) * lda + k0 + c * 8;
            const int so = r * ASTR + c * 8;
            cp16(ah + so, Agh + go);
            cp16(al + so, Agl + go);
        }
        #pragma unroll
        for (int i = tid; i < 512; i += 128) {
            const int r = i >> 4, c = i & 15;
            const long go = (long)(k0 + r) * ldb + n0 + c * 8;
            const int so = r * BSTR + c * 8;
            cp16(bh + so, Bgh + go);
            cp16(bl + so, Bgl + go);
        }
        cp_commit();
    };

    const int NST = K >> 5;
    loadStage(0, 0);
    if (NST > 1) loadStage(1, 32);

    for (int it = 0; it < NST; it++) {
        const int st = it % 3;
        if (it + 2 <= NST) asm volatile("cp.async.wait_group 1;" ::: "memory");
        else               asm volatile("cp.async.wait_group 0;" ::: "memory");
        __syncthreads();
        // issue next stage's loads BEFORE compute (buffer (it+2)%3 is free)
        if (it + 2 < NST) loadStage((it + 2) % 3, (it + 2) << 5);

        char* base = smem + st * STAGEB;
        const bf16* ah = (const bf16*)(base);
        const bf16* al = (const bf16*)(base + A_BYTES);
        const bf16* bh = (const bf16*)(base + 2 * A_BYTES);
        const bf16* bl = (const bf16*)(base + 2 * A_BYTES + B_BYTES);

        #pragma unroll
        for (int ks = 0; ks < 2; ks++) {
            uint32_t fAh[4][4], fAl[4][4];
            const int aoff = aoffL + ks * 16;
            #pragma unroll
            for (int mt = 0; mt < 4; mt++) {
                const int mb = (wm * 64 + mt * 16) * ASTR + aoff;
                ldsm4(fAh[mt], ah + mb);
                ldsm4(fAl[mt], al + mb);
            }
            const int brow = (ks * 16 + (lane & 15)) * BSTR + boffC;
            #pragma unroll
            for (int ph = 0; ph < 2; ph++) {      // two halves of 32 cols
                uint32_t fBh[4][2], fBl[4][2];
                #pragma unroll
                for (int p = 0; p < 2; p++) {
                    const int nb = brow + wn * 64 + ph * 32 + p * 16;
                    uint32_t r[4];
                    ldsm4t(r, bh + nb);
                    fBh[2*p][0] = r[0]; fBh[2*p][1] = r[1];
                    fBh[2*p+1][0] = r[2]; fBh[2*p+1][1] = r[3];
                    ldsm4t(r, bl + nb);
                    fBl[2*p][0] = r[0]; fBl[2*p][1] = r[1];
                    fBl[2*p+1][0] = r[2]; fBl[2*p+1][1] = r[3];
                }
                #pragma unroll
                for (int mt = 0; mt < 4; mt++)
                    #pragma unroll
                    for (int nt = 0; nt < 4; nt++) {
                        float* a4 = acc[mt][ph * 4 + nt];
                        mma_bf16(a4, fAh[mt], fBh[nt]);
                        mma_bf16(a4, fAh[mt], fBl[nt]);
                        mma_bf16(a4, fAl[mt], fBh[nt]);
                    }
            }
        }
    }

    // ---- epilogue ----
    #pragma unroll
    for (int mt = 0; mt < 4; mt++) {
        #pragma unroll
        for (int half = 0; half < 2; half++) {
            const int row = m0 + wm * 64 + mt * 16 + lr + half * 8;
            #pragma unroll
            for (int nt = 0; nt < 8; nt++) {
                const int col = n0 + wn * 64 + nt * 8 + 2 * lc;
                float v0 = acc[mt][nt][2 * half + 0];
                float v1 = acc[mt][nt][2 * half + 1];
                if (GLU) {
                    v0 += bias[col];
                    v1 += bias[col + 1];
                    float gv = v0 / (1.f + __expf(-v1));
                    if (GLUPAIR) {
                        const bool sec = col >= CC;
                        const int j = (sec ? col - CC : col) >> 1;
                        const float* st = sec ? styleS2 : styleS;
                        gv *= st[(row >> 11) * TD + j];
                        bf16 h, l;
                        split_bf16(gv, h, l);
                        const long o = (long)row * TD + j;
                        if (sec) { Ch2[o] = h; Cl2[o] = l; }
                        else     { Ch[o]  = h; Cl[o]  = l; }
                    } else {
                        const int j = col >> 1;
                        if (styleS) gv *= styleS[(row >> 11) * (N >> 1) + j];
                        bf16 h, l;
                        split_bf16(gv, h, l);
                        const long o = (long)row * (N >> 1) + j;
                        Ch[o] = h;
                        Cl[o] = l;
                    }
                } else {
                    if (bias) { v0 += bias[col]; v1 += bias[col + 1]; }
                    const long off = (long)row * N + col;
                    if (resp) {
                        float2 rv = *(const float2*)&resp[off];
                        v0 += rv.x; v1 += rv.y;
                    }
                    if (GELU) { v0 = gelu_f(v0); v1 = gelu_f(v1); }
                    if (FP32O) {
                        *(float2*)&Cf[(long)z * sC + off] = make_float2(v0, v1);
                    }
                    if (SPLIT) {
                        bf16 h0, l0, h1, l1;
                        split_bf16(v0, h0, l0);
                        split_bf16(v1, h1, l1);
                        if (TRANSO) {
                            // H1: (b,d,t)  b = row>>11, t = row&2047, d = col
                            const long o0 = ((long)(row >> 11) * TD + col) * TT + (row & 2047);
                            const long o1 = o0 + TT;
                            Ch[o0] = h0; Ch[o1] = h1;
                            Cl[o0] = l0; Cl[o1] = l1;
                        } else {
                            const long o = (long)z * sC + off;
                            *(__nv_bfloat162*)(Ch + o) = __nv_bfloat162(h0, h1);
                            *(__nv_bfloat162*)(Cl + o) = __nv_bfloat162(l0, l1);
                        }
                    }
                }
            }
        }
    }
}

// ---------------- host side --------------------------------------------------
static void* symp(const void* s) {
    void* p = nullptr;
    cudaGetSymbolAddress(&p, s);
    return p;
}

extern "C" void kernel_launch(void* const* d_in, const int* in_sizes, int n_in,
                              void* d_out, int out_size) {
    const float* x     = (const float*)d_in[0];
    const float* w     = (const float*)d_in[1];
    const float* ln1_g = (const float*)d_in[2];
    const float* ln1_b = (const float*)d_in[3];
    const float* ln2_g = (const float*)d_in[4];
    const float* ln2_b = (const float*)d_in[5];
    const float* g1_W  = (const float*)d_in[6];
    const float* g1_b  = (const float*)d_in[7];
    const float* s1_W  = (const float*)d_in[8];
    const float* s1_b  = (const float*)d_in[9];
    const float* m1_W  = (const float*)d_in[10];
    const float* m1_b  = (const float*)d_in[11];
    const float* g2_W  = (const float*)d_in[12];
    const float* g2_b  = (const float*)d_in[13];
    const float* s2_W  = (const float*)d_in[14];
    const float* s2_b  = (const float*)d_in[15];
    const float* m2_W  = (const float*)d_in[16];
    const float* m2_b  = (const float*)d_in[17];
    const float* gs_W  = (const float*)d_in[18];
    const float* gs_b  = (const float*)d_in[19];
    const float* ss_W  = (const float*)d_in[20];
    const float* ss_b  = (const float*)d_in[21];
    const float* ms_W  = (const float*)d_in[22];
    const float* ms_b  = (const float*)d_in[23];
    const float* r1_W  = (const float*)d_in[24];
    const float* r1_b  = (const float*)d_in[25];
    const float* r2_W  = (const float*)d_in[26];
    const float* r2_b  = (const float*)d_in[27];

    float* XLN = (float*)symp(BUF_XLN);
    float* X2  = (float*)symp(BUF_X2);
    float* S1  = (float*)symp(BUF_S1);
    float* S2  = (float*)symp(BUF_S2);
    float* SS  = (float*)symp(BUF_SS);
    float* BI  = (float*)symp(BUF_BI);
    bf16* XLNh = (bf16*)symp(S_XLNh);  bf16* XLNl = (bf16*)symp(S_XLNl);
    bf16* ACTh = (bf16*)symp(S_ACTh);  bf16* ACTl = (bf16*)symp(S_ACTl);
    bf16* A1h  = (bf16*)symp(S_A1h);   bf16* A1l  = (bf16*)symp(S_A1l);
    bf16* A2h  = (bf16*)symp(S_A2h);   bf16* A2l  = (bf16*)symp(S_A2l);
    bf16* H1h  = (bf16*)symp(S_H1h);   bf16* H1l  = (bf16*)symp(S_H1l);
    bf16* H2h  = (bf16*)symp(S_H2h);   bf16* H2l  = (bf16*)symp(S_H2l);
    bf16* MIXh = (bf16*)symp(S_MIXh);  bf16* MIXl = (bf16*)symp(S_MIXl);
    bf16* X3h  = (bf16*)symp(S_X3h);   bf16* X3l  = (bf16*)symp(S_X3l);
    bf16* Wh   = (bf16*)symp(S_Wh);    bf16* Wl   = (bf16*)symp(S_Wl);
    float* OUT = (float*)d_out;

    // dynamic smem opt-in (idempotent)
    cudaFuncSetAttribute(gemm_v4<true,  true,  false, false, false, false>,
                         cudaFuncAttributeMaxDynamicSharedMemorySize, SMEMB);
    cudaFuncSetAttribute(gemm_v4<true,  false, false, false, false, false>,
                         cudaFuncAttributeMaxDynamicSharedMemorySize, SMEMB);
    cudaFuncSetAttribute(gemm_v4<false, false, false, true,  true,  false>,
                         cudaFuncAttributeMaxDynamicSharedMemorySize, SMEMB);
    cudaFuncSetAttribute(gemm_v4<false, false, false, true,  false, false>,
                         cudaFuncAttributeMaxDynamicSharedMemorySize, SMEMB);
    cudaFuncSetAttribute(gemm_v4<false, false, true,  true,  false, false>,
                         cudaFuncAttributeMaxDynamicSharedMemorySize, SMEMB);
    cudaFuncSetAttribute(gemm_v4<false, false, false, false, false, true>,
                         cudaFuncAttributeMaxDynamicSharedMemorySize, SMEMB);

    // 1-2) pack g1|g2 into fused (768, 1536)
    glu_pack_w<<<(long)(CC*CC + 255)/256, 256>>>(g1_W, g1_b, Wh+OFF_G12, Wl+OFF_G12,
                                                 BI+BI_G12, (long)CC*CC, CC, 1536, 0);
    glu_pack_w<<<(long)(CC*CC + 255)/256, 256>>>(g2_W, g2_b, Wh+OFF_G12, Wl+OFF_G12,
                                                 BI+BI_G12, (long)CC*CC, CC, 1536, CC);
    // 3) ln1
    ln_split_kernel<<<ROWS, 256>>>(x, ln1_g, ln1_b, XLN, XLNh, XLNl, CC);
    // 4-5) style S1, S2
    style_s_kernel<<<dim3(TD/64, BB), dim3(64, 8)>>>(w, s1_W, s1_b, S1, 0, TD);
    style_s_kernel<<<dim3(TD/64, BB), dim3(64, 8)>>>(w, s2_W, s2_b, S2, 0, TD);
    // 6) fused GLU1|GLU2 GEMM (profiled by ncu)
    gemm_v4<true, true, false, false, false, false><<<dim3(1536/128, ROWS/128, 1), 128, SMEMB>>>(
        XLNh, XLNl, Wh+OFF_G12, Wl+OFF_G12, BI+BI_G12, S1, S2, nullptr,
        nullptr, A1h, A1l, A2h, A2l, 1536, CC, CC, 1536, 0, 0, 0, 0);
    // 7) cvt m1
    cvt_split_kernel<<<(TD*TD/4 + 255)/256, 256>>>((const float4*)m1_W, Wh+OFF_M1, Wl+OFF_M1, TD*TD/4);
    // 8) H1(trans) = A1@M1 + b
    gemm_v4<false, false, false, true, true, false><<<dim3(TD/128, ROWS/128, 1), 128, SMEMB>>>(
        A1h, A1l, Wh+OFF_M1, Wl+OFF_M1, m1_b, nullptr, nullptr, nullptr,
        nullptr, H1h, H1l, nullptr, nullptr, TD, TD, TD, TD, 0, 0, 0, 0);
    // 9) cvt m2
    cvt_split_kernel<<<(TD*TD/4 + 255)/256, 256>>>((const float4*)m2_W, Wh+OFF_M2, Wl+OFF_M2, TD*TD/4);
    // 10) H2 = A2@M2 + b
    gemm_v4<false, false, false, true, false, false><<<dim3(TD/128, ROWS/128, 1), 128, SMEMB>>>(
        A2h, A2l, Wh+OFF_M2, Wl+OFF_M2, m2_b, nullptr, nullptr, nullptr,
        nullptr, H2h, H2l, nullptr, nullptr, TD, TD, TD, TD, 0, 0, 0, 0);
    // 11) style SS
    style_s_kernel<<<dim3((CD/2)/64, BB), dim3(64, 8)>>>(w, ss_W, ss_b, SS, 1, CD/2);
    // 12) mix[b,d,c] = gelu(sum_t H1[b,d,t] * XLN[b,t,c])   M=TD, N=CC, K=TT
    gemm_v4<false, false, true, true, false, false><<<dim3(CC/128, TD/128, BB), 128, SMEMB>>>(
        H1h, H1l, XLNh, XLNl, nullptr, nullptr, nullptr, nullptr,
        nullptr, MIXh, MIXl, nullptr, nullptr, CC, TT, TT, CC,
        (long)TD*TT, (long)TT*CC, (long)TD*CC, 0);
    // 13) x2[b,t,c] = sum_d H2[b,t,d] * MIX[b,d,c] + xln    M=TT, N=CC, K=TD
    gemm_v4<false, false, false, false, false, true><<<dim3(CC/128, TT/128, BB), 128, SMEMB>>>(
        H2h, H2l, MIXh, MIXl, nullptr, nullptr, nullptr, XLN,
        X2, nullptr, nullptr, nullptr, nullptr, CC, TD, TD, CC,
        (long)TT*TD, (long)TD*CC, (long)TT*CC, (long)TT*CC);
    // 14) ln2
    ln_split_kernel<<<ROWS, 256>>>(X2, ln2_g, ln2_b, nullptr, XLNh, XLNl, CC);
    // 15) pack gs
    glu_pack_w<<<(long)(CC*CD + 255)/256, 256>>>(gs_W, gs_b, Wh+OFF_GS, Wl+OFF_GS,
                                                 BI+BI_GS, (long)CC*CD, CD, CD, 0);
    // 16) GLUs GEMM
    gemm_v4<true, false, false, false, false, false><<<dim3(CD/128, ROWS/128, 1), 128, SMEMB>>>(
        XLNh, XLNl, Wh+OFF_GS, Wl+OFF_GS, BI+BI_GS, SS, nullptr, nullptr,
        nullptr, ACTh, ACTl, nullptr, nullptr, CD, CC, CC, CD, 0, 0, 0, 0);
    // 17) cvt ms
    cvt_split_kernel<<<((CD/2)*CC/4 + 255)/256, 256>>>((const float4*)ms_W, Wh+OFF_MS, Wl+OFF_MS, (CD/2)*CC/4);
    // 18) X3 = ACT@MS + ms_b + X2
    gemm_v4<false, false, false, true, false, false><<<dim3(CC/128, ROWS/128, 1), 128, SMEMB>>>(
        ACTh, ACTl, Wh+OFF_MS, Wl+OFF_MS, ms_b, nullptr, nullptr, X2,
        nullptr, X3h, X3l, nullptr, nullptr, CC, CD/2, CD/2, CC, 0, 0, 0, 0);
    // 19) pack r1
    glu_pack_w<<<(long)(CC*CC + 255)/256, 256>>>(r1_W, r1_b, Wh+OFF_R1, Wl+OFF_R1,
                                                 BI+BI_R1, (long)CC*CC, CC, CC, 0);
    // 20) head GLU GEMM -> A1
    gemm_v4<true, false, false, false, false, false><<<dim3(CC/128, ROWS/128, 1), 128, SMEMB>>>(
        X3h, X3l, Wh+OFF_R1, Wl+OFF_R1, BI+BI_R1, nullptr, nullptr, nullptr,
        nullptr, A1h, A1l, nullptr, nullptr, CC, CC, CC, CC, 0, 0, 0, 0);
    // 21) cvt r2
    cvt_split_kernel<<<(TD*CC/4 + 255)/256, 256>>>((const float4*)r2_W, Wh+OFF_R2, Wl+OFF_R2, TD*CC/4);
    // 22) OUT = A1@R2 + b
    gemm_v4<false, false, false, false, false, true><<<dim3(CC/128, ROWS/128, 1), 128, SMEMB>>>(
        A1h, A1l, Wh+OFF_R2, Wl+OFF_R2, r2_b, nullptr, nullptr, nullptr,
        OUT, nullptr, nullptr, nullptr, nullptr, CC, TD, TD, CC, 0, 0, 0, 0);
}